// round 13
// baseline (speedup 1.0000x reference)
#include <cuda_runtime.h>
#include <cuda_fp16.h>

#define BB 256   // batch
#define SS 256   // seq len / steps
#define DD 128   // decoder dim
#define GG 512   // 4*D gates
#define TN 512   // lookup-table intervals

// fp16x2 LSTM hidden weights: g_Wpack[j*512 + u] = half2{W_hh[u][2j], W_hh[u][2j+1]},
// j = 0..63, u = gate 0..511. 128 KB; loaded into registers once per CTA.
__device__ __align__(16) unsigned int g_Wpack[32768];
__device__ float g_w1sum[SS];
__device__ float g_bias[GG];

__device__ __forceinline__ float tanh_fast(float x) {
    float y;
    asm("tanh.approx.f32 %0, %1;" : "=f"(y) : "f"(x));
    return y;
}
__device__ __forceinline__ float sigmoid_fast(float x) {
    return fmaf(tanh_fast(0.5f * x), 0.5f, 0.5f);
}
__device__ __forceinline__ unsigned long long pack2(float a, float b) {
    unsigned long long r;
    asm("mov.b64 %0, {%1,%2};" : "=l"(r) : "f"(a), "f"(b));
    return r;
}

// ---------------------------------------------------------------------------
// Prep kernel: pack W_hh, row-sum W1_w, fuse biases. One-time.
// ---------------------------------------------------------------------------
__global__ void prep_kernel(const float* __restrict__ W1_w,
                            const float* __restrict__ W_hh,
                            const float* __restrict__ b_ih,
                            const float* __restrict__ b_hh) {
    int blk = blockIdx.x;
    int t = threadIdx.x;
    if (blk < 128) {
        int idx = blk * 256 + t;          // 0..32767
        int j = idx >> 9;                 // k-pair 0..63
        int u = idx & 511;                // gate
        __half2 v = __halves2half2(__float2half_rn(W_hh[u * DD + 2 * j]),
                                   __float2half_rn(W_hh[u * DD + 2 * j + 1]));
        g_Wpack[idx] = *(unsigned int*)&v;
    } else {
        int lane = t & 31, w = t >> 5;
        for (int r = 0; r < 32; r++) {
            int s = w * 32 + r;
            float acc = 0.f;
            #pragma unroll
            for (int i = 0; i < 8; i++) acc += W1_w[s * SS + lane + 32 * i];
            #pragma unroll
            for (int off = 16; off; off >>= 1)
                acc += __shfl_xor_sync(0xffffffffu, acc, off);
            if (lane == 0) g_w1sum[s] = acc;
        }
        g_bias[t]       = b_ih[t]       + b_hh[t];
        g_bias[t + 256] = b_ih[t + 256] + b_hh[t + 256];
    }
}

// ---------------------------------------------------------------------------
// Main kernel: 2 batch elements per CTA, 1024 threads (64-reg budget), 256
// LSTM steps. Thread (u = gate, kh = k-half) holds 32 half2 weight registers
// (FULLY unrolled -> true registers), computes both batches with packed
// f32x2 FMA; k-half partials combine via 8 KB smem. Attention collapsed to
// per-batch lerp tables (built once).
// ---------------------------------------------------------------------------
__global__ __launch_bounds__(1024, 1)
void decoder_kernel(const float* __restrict__ enc,   // [B,S,E]
                    const float* __restrict__ W1_b,  // [S]
                    const float* __restrict__ W2_w,  // [S,2S]
                    const float* __restrict__ W2_b,  // [S]
                    const float* __restrict__ W_ih,  // [4D,E]
                    float* __restrict__ out)         // [S,B,D]
{
    __shared__ __align__(16) float4 sAC[2][128];
    __shared__ __align__(16) float4 sE[2][128];
    __shared__ __align__(16) float  ebuf[1024];
    __shared__ float a_st[2][256];
    __shared__ __align__(16) float4 Ttab[2][TN];   // {g0x,g0y,dgx,dgy}
    __shared__ float2 tail2[2];
    __shared__ __align__(16) float gph[2][2][GG];  // [kh][m][u] partial gates
    __shared__ __align__(16) float h_s[2][DD];
    __shared__ __align__(16) float2 wred[2][4];
    __shared__ __align__(16) float2 wihs[GG];
    __shared__ float sbias[GG];

    const int bid = blockIdx.x;
    const int t = threadIdx.x;        // 0..1023
    const int lane = t & 31;
    const int warp = t >> 5;

    // ---- init loads ----
    ebuf[t] = enc[bid * 1024 + t];
    if (t < GG) { wihs[t] = ((const float2*)W_ih)[t]; sbias[t] = g_bias[t]; }
    if (t < 256) h_s[t >> 7][t & 127] = 0.f;
    __syncthreads();

    // a[m][s] = encflat[m] . W2_w[s,:] + W2_b[s] + W1_b[s]; 32 warps x 16 rows
    {
        const int m_w = warp >> 4;                  // warps 0-15: m=0, 16-31: m=1
        const float4* W2w4 = (const float4*)W2_w;
        const float4* e4   = (const float4*)(ebuf + m_w * 512);
        for (int r = 0; r < 16; r++) {
            int s = (warp & 15) * 16 + r;
            float acc = 0.f;
            #pragma unroll
            for (int i = 0; i < 4; i++) {
                float4 wv = W2w4[s * 128 + lane + 32 * i];
                float4 ev = e4[lane + 32 * i];
                acc += wv.x * ev.x + wv.y * ev.y + wv.z * ev.z + wv.w * ev.w;
            }
            #pragma unroll
            for (int off = 16; off; off >>= 1)
                acc += __shfl_xor_sync(0xffffffffu, acc, off);
            if (lane == 0) a_st[m_w][s] = acc + W2_b[s] + W1_b[s];
        }
    }
    __syncthreads();
    if (t < 256) {
        int m = t >> 7, p = t & 127;
        sAC[m][p] = make_float4(a_st[m][2 * p], a_st[m][2 * p + 1],
                                g_w1sum[2 * p], g_w1sum[2 * p + 1]);
        sE[m][p]  = make_float4(ebuf[m * 512 + 4 * p],     ebuf[m * 512 + 4 * p + 2],
                                ebuf[m * 512 + 4 * p + 1], ebuf[m * 512 + 4 * p + 3]);
    }
    __syncthreads();

    // Degree-5 Chebyshev-economized poly for exp(t), t in [-1,1], abs err <= 5e-5
    const unsigned long long P5 = pack2(0.00868688f, 0.00868688f);
    const unsigned long long P4 = pack2(0.04379392f, 0.04379392f);
    const unsigned long long P3 = pack2(0.16648880f, 0.16648880f);
    const unsigned long long P2 = pack2(0.49919676f, 0.49919676f);
    const unsigned long long P1 = pack2(1.00002231f, 1.00002231f);
    const unsigned long long P0 = pack2(1.00004478f, 1.00004478f);

    // ---- build lookup tables ----
    for (int idx = t; idx < 2 * (TN + 1); idx += 1024) {
        int m = (idx > TN) ? 1 : 0;
        int k = idx - m * (TN + 1);
        const double2* pAC = (const double2*)sAC[m];
        const double2* pE  = (const double2*)sE[m];
        float h = fmaf((float)k, 2.0f / TN, -1.0f);
        unsigned long long hd2;
        asm("mov.b64 %0, {%1,%1};" : "=l"(hd2) : "f"(h));
        unsigned long long Z2 = 0ull, n02 = 0ull, n12 = 0ull;
        #pragma unroll 4
        for (int i = 0; i < 128; i++) {
            double2 acd = pAC[i];
            double2 eed = pE[i];
            unsigned long long ap  = __double_as_longlong(acd.x);
            unsigned long long cp  = __double_as_longlong(acd.y);
            unsigned long long e0p = __double_as_longlong(eed.x);
            unsigned long long e1p = __double_as_longlong(eed.y);
            unsigned long long x2;
            asm("fma.rn.f32x2 %0, %1, %2, %3;" : "=l"(x2) : "l"(hd2), "l"(cp), "l"(ap));
            float x0, x1;
            asm("mov.b64 {%0,%1}, %2;" : "=f"(x0), "=f"(x1) : "l"(x2));
            float t0 = tanh_fast(x0);
            float t1 = tanh_fast(x1);
            unsigned long long t2;
            asm("mov.b64 %0, {%1,%2};" : "=l"(t2) : "f"(t0), "f"(t1));
            unsigned long long p;
            asm("fma.rn.f32x2 %0, %1, %2, %3;" : "=l"(p) : "l"(P5), "l"(t2), "l"(P4));
            asm("fma.rn.f32x2 %0, %0, %1, %2;" : "+l"(p) : "l"(t2), "l"(P3));
            asm("fma.rn.f32x2 %0, %0, %1, %2;" : "+l"(p) : "l"(t2), "l"(P2));
            asm("fma.rn.f32x2 %0, %0, %1, %2;" : "+l"(p) : "l"(t2), "l"(P1));
            asm("fma.rn.f32x2 %0, %0, %1, %2;" : "+l"(p) : "l"(t2), "l"(P0));
            asm("add.rn.f32x2 %0, %0, %1;"     : "+l"(Z2) : "l"(p));
            asm("fma.rn.f32x2 %0, %1, %2, %0;" : "+l"(n02) : "l"(p), "l"(e0p));
            asm("fma.rn.f32x2 %0, %1, %2, %0;" : "+l"(n12) : "l"(p), "l"(e1p));
        }
        float Zl, Zh, a0, a1, b0, b1;
        asm("mov.b64 {%0,%1}, %2;" : "=f"(Zl), "=f"(Zh) : "l"(Z2));
        asm("mov.b64 {%0,%1}, %2;" : "=f"(a0), "=f"(a1) : "l"(n02));
        asm("mov.b64 {%0,%1}, %2;" : "=f"(b0), "=f"(b1) : "l"(n12));
        float Z = Zl + Zh, n0 = a0 + a1, n1 = b0 + b1;
        float inv = __fdividef(1.f, Z);
        float gx = n0 * inv, gy = n1 * inv;
        if (k < TN) { Ttab[m][k].x = gx; Ttab[m][k].y = gy; }
        else        { tail2[m] = make_float2(gx, gy); }
    }
    __syncthreads();
    {   // slopes: exactly 1024 items = 1 per thread
        int m = t >> 9, k = t & (TN - 1);
        float2 cur = *(const float2*)&Ttab[m][k];
        float2 nxt = (k == TN - 1) ? tail2[m] : *(const float2*)&Ttab[m][k + 1];
        __syncthreads();
        Ttab[m][k].z = nxt.x - cur.x;
        Ttab[m][k].w = nxt.y - cur.y;
    }
    __syncthreads();

    // ---- roles + register weight load (32 uints, FULL unroll) ----
    const int u  = t & 511;           // gate
    const int kh = t >> 9;            // k-half (warp-uniform)
    unsigned int Wr[32];
    {
        const unsigned int* wsrc = g_Wpack + kh * 32 * 512 + u;
        #pragma unroll
        for (int j = 0; j < 32; j++) Wr[j] = wsrc[j * 512];   // coalesced, one-time
    }
    const unsigned long long bias2 = (kh == 0) ? pack2(sbias[u], 0.f) : 0ull;
    float c_reg = 0.f;                // cell state for epilogue threads (0..255)

    const double2* H0 = (const double2*)(h_s[0]) + kh * 16;
    const double2* H1 = (const double2*)(h_s[1]) + kh * 16;

    for (int step = 0; step < SS; step++) {
        // ---- Phase 1a: half-dot for both batches (f32x2 FMA, regs) ----
        unsigned long long A0 = bias2, A1 = bias2;
        #pragma unroll
        for (int j = 0; j < 16; j++) {
            double2 hp0 = H0[j];                    // LDS.128 broadcast
            double2 hp1 = H1[j];
            float2 wa = __half22float2(*(const __half2*)&Wr[2 * j]);
            float2 wb = __half22float2(*(const __half2*)&Wr[2 * j + 1]);
            unsigned long long WA = pack2(wa.x, wa.y);
            unsigned long long WB = pack2(wb.x, wb.y);
            asm("fma.rn.f32x2 %0, %1, %2, %0;" : "+l"(A0)
                : "l"(__double_as_longlong(hp0.x)), "l"(WA));
            asm("fma.rn.f32x2 %0, %1, %2, %0;" : "+l"(A1)
                : "l"(__double_as_longlong(hp1.x)), "l"(WA));
            asm("fma.rn.f32x2 %0, %1, %2, %0;" : "+l"(A0)
                : "l"(__double_as_longlong(hp0.y)), "l"(WB));
            asm("fma.rn.f32x2 %0, %1, %2, %0;" : "+l"(A1)
                : "l"(__double_as_longlong(hp1.y)), "l"(WB));
        }
        {
            float g0l, g0h, g1l, g1h;
            asm("mov.b64 {%0,%1}, %2;" : "=f"(g0l), "=f"(g0h) : "l"(A0));
            asm("mov.b64 {%0,%1}, %2;" : "=f"(g1l), "=f"(g1h) : "l"(A1));
            gph[kh][0][u] = g0l + g0h;
            gph[kh][1][u] = g1l + g1h;
        }

        // ---- Phase 1b: attention lookup (warps 8..15: one (m,d) each) ----
        if (t >= 256 && t < 512) {
            int tt = t - 256;
            int m = tt >> 7, d2 = tt & 127;
            float h = h_s[m][d2];
            float uu = fmaf(h, (float)(TN / 2), (float)(TN / 2));
            int i = (int)uu;
            i = max(0, min(i, TN - 1));
            float f = uu - (float)i;
            float4 tv = Ttab[m][i];
            float gx = fmaf(f, tv.z, tv.x);
            float gy = fmaf(f, tv.w, tv.y);
            #pragma unroll
            for (int off = 16; off; off >>= 1) {
                gx += __shfl_xor_sync(0xffffffffu, gx, off);
                gy += __shfl_xor_sync(0xffffffffu, gy, off);
            }
            if (lane == 0) wred[m][(warp - 8) & 3] = make_float2(gx, gy);
        }
        __syncthreads();                         // B1

        // ---- Phase 2: ctx-combine + LSTM update (threads 0..255) ----
        if (t < 256) {
            int m = t >> 7, d = t & 127;
            float2 r0 = wred[m][0], r1 = wred[m][1], r2 = wred[m][2], r3 = wred[m][3];
            float x0c = (r0.x + r1.x + r2.x + r3.x) * (1.f / 128.f);
            float x1c = (r0.y + r1.y + r2.y + r3.y) * (1.f / 128.f);
            float2 wi0 = wihs[d];
            float2 wi1 = wihs[d + 128];
            float2 wi2 = wihs[d + 256];
            float2 wi3 = wihs[d + 384];
            float gi = gph[0][m][d]       + gph[1][m][d]       + x0c * wi0.x + x1c * wi0.y;
            float gf = gph[0][m][d + 128] + gph[1][m][d + 128] + x0c * wi1.x + x1c * wi1.y;
            float gg = gph[0][m][d + 256] + gph[1][m][d + 256] + x0c * wi2.x + x1c * wi2.y;
            float go = gph[0][m][d + 384] + gph[1][m][d + 384] + x0c * wi3.x + x1c * wi3.y;
            float si = sigmoid_fast(gi);
            float sf = sigmoid_fast(gf);
            float so = sigmoid_fast(go);
            c_reg = fmaf(sf, c_reg, si * tanh_fast(gg));
            float h = so * tanh_fast(c_reg);
            h_s[m][d] = h;
            out[(size_t)step * (BB * DD) + (2 * bid + m) * DD + d] = h;
        }
        __syncthreads();                         // B2
    }
}

// ---------------------------------------------------------------------------
extern "C" void kernel_launch(void* const* d_in, const int* in_sizes, int n_in,
                              void* d_out, int out_size) {
    const float* enc  = (const float*)d_in[0];
    const float* W1_w = (const float*)d_in[1];
    const float* W1_b = (const float*)d_in[2];
    const float* W2_w = (const float*)d_in[3];
    const float* W2_b = (const float*)d_in[4];
    const float* W_ih = (const float*)d_in[5];
    const float* W_hh = (const float*)d_in[6];
    const float* b_ih = (const float*)d_in[7];
    const float* b_hh = (const float*)d_in[8];
    float* out = (float*)d_out;

    prep_kernel<<<129, 256>>>(W1_w, W_hh, b_ih, b_hh);
    decoder_kernel<<<BB / 2, 1024>>>(enc, W1_b, W2_w, W2_b, W_ih, out);
}

// round 14
// speedup vs baseline: 1.6668x; 1.6668x over previous
#include <cuda_runtime.h>
#include <cuda_fp16.h>

#define BB 256   // batch
#define SS 256   // seq len / steps
#define DD 128   // decoder dim
#define GG 512   // 4*D gates
#define TN 512   // lookup-table intervals

// fp16x2 LSTM hidden weights, streamed per step via LDG.128 (L1-resident).
// uint4 block i (0..7) of thread thr=(kh*512+u): 4 k-pairs p = kh*32+4i+m.
// flat uint idx = (i*1024 + thr)*4 + m = half2{ W_hh[u][2p], W_hh[u][2p+1] }.
__device__ __align__(16) unsigned int g_Wpack[32768];
__device__ float g_w1sum[SS];
__device__ float g_bias[GG];

__device__ __forceinline__ float tanh_fast(float x) {
    float y;
    asm("tanh.approx.f32 %0, %1;" : "=f"(y) : "f"(x));
    return y;
}
__device__ __forceinline__ float sigmoid_fast(float x) {
    return fmaf(tanh_fast(0.5f * x), 0.5f, 0.5f);
}
__device__ __forceinline__ unsigned long long pack2(float a, float b) {
    unsigned long long r;
    asm("mov.b64 %0, {%1,%2};" : "=l"(r) : "f"(a), "f"(b));
    return r;
}

// ---------------------------------------------------------------------------
// Prep kernel: pack W_hh, row-sum W1_w, fuse biases. One-time.
// ---------------------------------------------------------------------------
__global__ void prep_kernel(const float* __restrict__ W1_w,
                            const float* __restrict__ W_hh,
                            const float* __restrict__ b_ih,
                            const float* __restrict__ b_hh) {
    int blk = blockIdx.x;
    int t = threadIdx.x;
    if (blk < 128) {
        int idx = blk * 256 + t;          // 0..32767
        int m   = idx & 3;
        int thr = (idx >> 2) & 1023;
        int i   = idx >> 12;              // uint4 block 0..7
        int u   = thr & 511;
        int kh  = thr >> 9;
        int p   = kh * 32 + i * 4 + m;    // k-pair
        __half2 v = __halves2half2(__float2half_rn(W_hh[u * DD + 2 * p]),
                                   __float2half_rn(W_hh[u * DD + 2 * p + 1]));
        g_Wpack[idx] = *(unsigned int*)&v;
    } else {
        int lane = t & 31, w = t >> 5;
        for (int r = 0; r < 32; r++) {
            int s = w * 32 + r;
            float acc = 0.f;
            #pragma unroll
            for (int i = 0; i < 8; i++) acc += W1_w[s * SS + lane + 32 * i];
            #pragma unroll
            for (int off = 16; off; off >>= 1)
                acc += __shfl_xor_sync(0xffffffffu, acc, off);
            if (lane == 0) g_w1sum[s] = acc;
        }
        g_bias[t]       = b_ih[t]       + b_hh[t];
        g_bias[t + 256] = b_ih[t + 256] + b_hh[t + 256];
    }
}

// ---------------------------------------------------------------------------
// Main kernel: 2 batch elements per CTA, 1024 threads, 256 LSTM steps.
// Thread (u = gate, kh = k-half) STREAMS its 32 weight pairs from L1 via
// 8 x LDG.128 each step (no register array -> ~40 live regs, no spills),
// computes both batches with packed f32x2 FMA; k-half partials combine via
// smem. Attention collapsed to per-batch lerp tables (built once).
// ---------------------------------------------------------------------------
__global__ __launch_bounds__(1024, 1)
void decoder_kernel(const float* __restrict__ enc,   // [B,S,E]
                    const float* __restrict__ W1_b,  // [S]
                    const float* __restrict__ W2_w,  // [S,2S]
                    const float* __restrict__ W2_b,  // [S]
                    const float* __restrict__ W_ih,  // [4D,E]
                    float* __restrict__ out)         // [S,B,D]
{
    __shared__ __align__(16) float4 sAC[2][128];
    __shared__ __align__(16) float4 sE[2][128];
    __shared__ __align__(16) float  ebuf[1024];
    __shared__ float a_st[2][256];
    __shared__ __align__(16) float4 Ttab[2][TN];   // {g0x,g0y,dgx,dgy}
    __shared__ float2 tail2[2];
    __shared__ __align__(16) float gph[2][2][GG];  // [kh][m][u] partial gates
    __shared__ __align__(16) float h_s[2][DD];
    __shared__ __align__(16) float2 wred[2][4];
    __shared__ __align__(16) float2 wihs[GG];
    __shared__ float sbias[GG];

    const int bid = blockIdx.x;
    const int t = threadIdx.x;        // 0..1023
    const int lane = t & 31;
    const int warp = t >> 5;

    // ---- init loads ----
    ebuf[t] = enc[bid * 1024 + t];
    if (t < GG) { wihs[t] = ((const float2*)W_ih)[t]; sbias[t] = g_bias[t]; }
    if (t < 256) h_s[t >> 7][t & 127] = 0.f;
    __syncthreads();

    // a[m][s] = encflat[m] . W2_w[s,:] + W2_b[s] + W1_b[s]; 32 warps x 16 rows
    {
        const int m_w = warp >> 4;                  // warps 0-15: m=0, 16-31: m=1
        const float4* W2w4 = (const float4*)W2_w;
        const float4* e4   = (const float4*)(ebuf + m_w * 512);
        for (int r = 0; r < 16; r++) {
            int s = (warp & 15) * 16 + r;
            float acc = 0.f;
            #pragma unroll
            for (int i = 0; i < 4; i++) {
                float4 wv = W2w4[s * 128 + lane + 32 * i];
                float4 ev = e4[lane + 32 * i];
                acc += wv.x * ev.x + wv.y * ev.y + wv.z * ev.z + wv.w * ev.w;
            }
            #pragma unroll
            for (int off = 16; off; off >>= 1)
                acc += __shfl_xor_sync(0xffffffffu, acc, off);
            if (lane == 0) a_st[m_w][s] = acc + W2_b[s] + W1_b[s];
        }
    }
    __syncthreads();
    if (t < 256) {
        int m = t >> 7, p = t & 127;
        sAC[m][p] = make_float4(a_st[m][2 * p], a_st[m][2 * p + 1],
                                g_w1sum[2 * p], g_w1sum[2 * p + 1]);
        sE[m][p]  = make_float4(ebuf[m * 512 + 4 * p],     ebuf[m * 512 + 4 * p + 2],
                                ebuf[m * 512 + 4 * p + 1], ebuf[m * 512 + 4 * p + 3]);
    }
    __syncthreads();

    // Degree-5 Chebyshev-economized poly for exp(t), t in [-1,1], abs err <= 5e-5
    const unsigned long long P5 = pack2(0.00868688f, 0.00868688f);
    const unsigned long long P4 = pack2(0.04379392f, 0.04379392f);
    const unsigned long long P3 = pack2(0.16648880f, 0.16648880f);
    const unsigned long long P2 = pack2(0.49919676f, 0.49919676f);
    const unsigned long long P1 = pack2(1.00002231f, 1.00002231f);
    const unsigned long long P0 = pack2(1.00004478f, 1.00004478f);

    // ---- build lookup tables ----
    for (int idx = t; idx < 2 * (TN + 1); idx += 1024) {
        int m = (idx > TN) ? 1 : 0;
        int k = idx - m * (TN + 1);
        const double2* pAC = (const double2*)sAC[m];
        const double2* pE  = (const double2*)sE[m];
        float h = fmaf((float)k, 2.0f / TN, -1.0f);
        unsigned long long hd2;
        asm("mov.b64 %0, {%1,%1};" : "=l"(hd2) : "f"(h));
        unsigned long long Z2 = 0ull, n02 = 0ull, n12 = 0ull;
        #pragma unroll 4
        for (int i = 0; i < 128; i++) {
            double2 acd = pAC[i];
            double2 eed = pE[i];
            unsigned long long ap  = __double_as_longlong(acd.x);
            unsigned long long cp  = __double_as_longlong(acd.y);
            unsigned long long e0p = __double_as_longlong(eed.x);
            unsigned long long e1p = __double_as_longlong(eed.y);
            unsigned long long x2;
            asm("fma.rn.f32x2 %0, %1, %2, %3;" : "=l"(x2) : "l"(hd2), "l"(cp), "l"(ap));
            float x0, x1;
            asm("mov.b64 {%0,%1}, %2;" : "=f"(x0), "=f"(x1) : "l"(x2));
            float t0 = tanh_fast(x0);
            float t1 = tanh_fast(x1);
            unsigned long long t2;
            asm("mov.b64 %0, {%1,%2};" : "=l"(t2) : "f"(t0), "f"(t1));
            unsigned long long p;
            asm("fma.rn.f32x2 %0, %1, %2, %3;" : "=l"(p) : "l"(P5), "l"(t2), "l"(P4));
            asm("fma.rn.f32x2 %0, %0, %1, %2;" : "+l"(p) : "l"(t2), "l"(P3));
            asm("fma.rn.f32x2 %0, %0, %1, %2;" : "+l"(p) : "l"(t2), "l"(P2));
            asm("fma.rn.f32x2 %0, %0, %1, %2;" : "+l"(p) : "l"(t2), "l"(P1));
            asm("fma.rn.f32x2 %0, %0, %1, %2;" : "+l"(p) : "l"(t2), "l"(P0));
            asm("add.rn.f32x2 %0, %0, %1;"     : "+l"(Z2) : "l"(p));
            asm("fma.rn.f32x2 %0, %1, %2, %0;" : "+l"(n02) : "l"(p), "l"(e0p));
            asm("fma.rn.f32x2 %0, %1, %2, %0;" : "+l"(n12) : "l"(p), "l"(e1p));
        }
        float Zl, Zh, a0, a1, b0, b1;
        asm("mov.b64 {%0,%1}, %2;" : "=f"(Zl), "=f"(Zh) : "l"(Z2));
        asm("mov.b64 {%0,%1}, %2;" : "=f"(a0), "=f"(a1) : "l"(n02));
        asm("mov.b64 {%0,%1}, %2;" : "=f"(b0), "=f"(b1) : "l"(n12));
        float Z = Zl + Zh, n0 = a0 + a1, n1 = b0 + b1;
        float inv = __fdividef(1.f, Z);
        float gx = n0 * inv, gy = n1 * inv;
        if (k < TN) { Ttab[m][k].x = gx; Ttab[m][k].y = gy; }
        else        { tail2[m] = make_float2(gx, gy); }
    }
    __syncthreads();
    {   // slopes: exactly 1024 items = 1 per thread
        int m = t >> 9, k = t & (TN - 1);
        float2 cur = *(const float2*)&Ttab[m][k];
        float2 nxt = (k == TN - 1) ? tail2[m] : *(const float2*)&Ttab[m][k + 1];
        __syncthreads();
        Ttab[m][k].z = nxt.x - cur.x;
        Ttab[m][k].w = nxt.y - cur.y;
    }
    __syncthreads();

    // ---- roles (weights streamed, NOT register-resident) ----
    const int u  = t & 511;           // gate
    const int kh = t >> 9;            // k-half (warp-uniform)
    const uint4* Wsrc4 = ((const uint4*)g_Wpack) + t;   // + i*1024 per block
    const unsigned long long bias2 = (kh == 0) ? pack2(sbias[u], 0.f) : 0ull;
    float c_reg = 0.f;                // cell state for epilogue threads (0..255)

    const double2* H0 = ((const double2*)h_s[0]) + kh * 16;
    const double2* H1 = ((const double2*)h_s[1]) + kh * 16;

    for (int step = 0; step < SS; step++) {
        // ---- Phase 1a: half-dot for both batches (weights via LDG.128) ----
        unsigned long long A0 = bias2, A1 = bias2;
        #pragma unroll
        for (int i = 0; i < 8; i++) {
            uint4 wr = Wsrc4[i * 1024];             // LDG.128, L1-resident
            double2 hp0a = H0[2 * i];               // LDS.128 broadcast
            double2 hp0b = H0[2 * i + 1];
            double2 hp1a = H1[2 * i];
            double2 hp1b = H1[2 * i + 1];
            float2 f0 = __half22float2(*(const __half2*)&wr.x);  // k {8i+0,1}
            float2 f1 = __half22float2(*(const __half2*)&wr.y);  // k {8i+2,3}
            float2 f2 = __half22float2(*(const __half2*)&wr.z);  // k {8i+4,5}
            float2 f3 = __half22float2(*(const __half2*)&wr.w);  // k {8i+6,7}
            unsigned long long W0 = pack2(f0.x, f0.y);
            unsigned long long W1 = pack2(f1.x, f1.y);
            unsigned long long W2 = pack2(f2.x, f2.y);
            unsigned long long W3 = pack2(f3.x, f3.y);
            asm("fma.rn.f32x2 %0, %1, %2, %0;" : "+l"(A0)
                : "l"(__double_as_longlong(hp0a.x)), "l"(W0));
            asm("fma.rn.f32x2 %0, %1, %2, %0;" : "+l"(A1)
                : "l"(__double_as_longlong(hp1a.x)), "l"(W0));
            asm("fma.rn.f32x2 %0, %1, %2, %0;" : "+l"(A0)
                : "l"(__double_as_longlong(hp0a.y)), "l"(W1));
            asm("fma.rn.f32x2 %0, %1, %2, %0;" : "+l"(A1)
                : "l"(__double_as_longlong(hp1a.y)), "l"(W1));
            asm("fma.rn.f32x2 %0, %1, %2, %0;" : "+l"(A0)
                : "l"(__double_as_longlong(hp0b.x)), "l"(W2));
            asm("fma.rn.f32x2 %0, %1, %2, %0;" : "+l"(A1)
                : "l"(__double_as_longlong(hp1b.x)), "l"(W2));
            asm("fma.rn.f32x2 %0, %1, %2, %0;" : "+l"(A0)
                : "l"(__double_as_longlong(hp0b.y)), "l"(W3));
            asm("fma.rn.f32x2 %0, %1, %2, %0;" : "+l"(A1)
                : "l"(__double_as_longlong(hp1b.y)), "l"(W3));
        }
        {
            float g0l, g0h, g1l, g1h;
            asm("mov.b64 {%0,%1}, %2;" : "=f"(g0l), "=f"(g0h) : "l"(A0));
            asm("mov.b64 {%0,%1}, %2;" : "=f"(g1l), "=f"(g1h) : "l"(A1));
            gph[kh][0][u] = g0l + g0h;
            gph[kh][1][u] = g1l + g1h;
        }

        // ---- Phase 1b: attention lookup (warps 8..15: one (m,d) each) ----
        if (t >= 256 && t < 512) {
            int tt = t - 256;
            int m = tt >> 7, d2 = tt & 127;
            float h = h_s[m][d2];
            float uu = fmaf(h, (float)(TN / 2), (float)(TN / 2));
            int i = (int)uu;
            i = max(0, min(i, TN - 1));
            float f = uu - (float)i;
            float4 tv = Ttab[m][i];
            float gx = fmaf(f, tv.z, tv.x);
            float gy = fmaf(f, tv.w, tv.y);
            #pragma unroll
            for (int off = 16; off; off >>= 1) {
                gx += __shfl_xor_sync(0xffffffffu, gx, off);
                gy += __shfl_xor_sync(0xffffffffu, gy, off);
            }
            if (lane == 0) wred[m][(warp - 8) & 3] = make_float2(gx, gy);
        }
        __syncthreads();                         // B1

        // ---- Phase 2: ctx-combine + LSTM update (threads 0..255) ----
        if (t < 256) {
            int m = t >> 7, d = t & 127;
            float2 r0 = wred[m][0], r1 = wred[m][1], r2 = wred[m][2], r3 = wred[m][3];
            float x0c = (r0.x + r1.x + r2.x + r3.x) * (1.f / 128.f);
            float x1c = (r0.y + r1.y + r2.y + r3.y) * (1.f / 128.f);
            float2 wi0 = wihs[d];
            float2 wi1 = wihs[d + 128];
            float2 wi2 = wihs[d + 256];
            float2 wi3 = wihs[d + 384];
            float gi = gph[0][m][d]       + gph[1][m][d]       + x0c * wi0.x + x1c * wi0.y;
            float gf = gph[0][m][d + 128] + gph[1][m][d + 128] + x0c * wi1.x + x1c * wi1.y;
            float gg = gph[0][m][d + 256] + gph[1][m][d + 256] + x0c * wi2.x + x1c * wi2.y;
            float go = gph[0][m][d + 384] + gph[1][m][d + 384] + x0c * wi3.x + x1c * wi3.y;
            float si = sigmoid_fast(gi);
            float sf = sigmoid_fast(gf);
            float so = sigmoid_fast(go);
            c_reg = fmaf(sf, c_reg, si * tanh_fast(gg));
            float h = so * tanh_fast(c_reg);
            h_s[m][d] = h;
            out[(size_t)step * (BB * DD) + (2 * bid + m) * DD + d] = h;
        }
        __syncthreads();                         // B2
    }
}

// ---------------------------------------------------------------------------
extern "C" void kernel_launch(void* const* d_in, const int* in_sizes, int n_in,
                              void* d_out, int out_size) {
    const float* enc  = (const float*)d_in[0];
    const float* W1_w = (const float*)d_in[1];
    const float* W1_b = (const float*)d_in[2];
    const float* W2_w = (const float*)d_in[3];
    const float* W2_b = (const float*)d_in[4];
    const float* W_ih = (const float*)d_in[5];
    const float* W_hh = (const float*)d_in[6];
    const float* b_ih = (const float*)d_in[7];
    const float* b_hh = (const float*)d_in[8];
    float* out = (float*)d_out;

    prep_kernel<<<129, 256>>>(W1_w, W_hh, b_ih, b_hh);
    decoder_kernel<<<BB / 2, 1024>>>(enc, W1_b, W2_w, W2_b, W_ih, out);
}

// round 15
// speedup vs baseline: 3.2182x; 1.9308x over previous
#include <cuda_runtime.h>
#include <cuda_fp16.h>

#define BB 256   // batch
#define SS 256   // seq len / steps
#define DD 128   // decoder dim
#define GG 512   // 4*D gates
#define TN 512   // lookup-table intervals

// W_hh packed as mma.m16n8k16 A-fragments (fp16, row-major A = [gate][k]).
// Entry (c*1024 + t)*4 + r, r=0..3:
//   w = t>>5, l = t&31, g = l>>2, q = l&3
//   row = 16w + g + (r&1 ? 8 : 0),  k = 16c + 2q + (r&2 ? 8 : 0)
//   value = half2{ W_hh[row][k], W_hh[row][k+1] }
__device__ __align__(16) unsigned int g_Wfrag[32768];
__device__ float g_w1sum[SS];
__device__ float g_bias[GG];

__device__ __forceinline__ float tanh_fast(float x) {
    float y;
    asm("tanh.approx.f32 %0, %1;" : "=f"(y) : "f"(x));
    return y;
}
__device__ __forceinline__ float sigmoid_fast(float x) {
    return fmaf(tanh_fast(0.5f * x), 0.5f, 0.5f);
}
__device__ __forceinline__ unsigned long long pack2(float a, float b) {
    unsigned long long r;
    asm("mov.b64 %0, {%1,%2};" : "=l"(r) : "f"(a), "f"(b));
    return r;
}

// ---------------------------------------------------------------------------
// Prep kernel: pack W_hh into mma A-fragments, row-sum W1_w, fuse biases.
// ---------------------------------------------------------------------------
__global__ void prep_kernel(const float* __restrict__ W1_w,
                            const float* __restrict__ W_hh,
                            const float* __restrict__ b_ih,
                            const float* __restrict__ b_hh) {
    int blk = blockIdx.x;
    int t = threadIdx.x;
    if (blk < 128) {
        int idx = blk * 256 + t;          // 0..32767
        int r   = idx & 3;
        int thr = (idx >> 2) & 1023;
        int c   = idx >> 12;              // k-chunk 0..7
        int w = thr >> 5, l = thr & 31;
        int g = l >> 2, q = l & 3;
        int row = 16 * w + g + ((r & 1) ? 8 : 0);
        int k   = 16 * c + 2 * q + ((r & 2) ? 8 : 0);
        __half2 v = __halves2half2(__float2half_rn(W_hh[row * DD + k]),
                                   __float2half_rn(W_hh[row * DD + k + 1]));
        g_Wfrag[idx] = *(unsigned int*)&v;
    } else {
        int lane = t & 31, w = t >> 5;
        for (int r = 0; r < 32; r++) {
            int s = w * 32 + r;
            float acc = 0.f;
            #pragma unroll
            for (int i = 0; i < 8; i++) acc += W1_w[s * SS + lane + 32 * i];
            #pragma unroll
            for (int off = 16; off; off >>= 1)
                acc += __shfl_xor_sync(0xffffffffu, acc, off);
            if (lane == 0) g_w1sum[s] = acc;
        }
        g_bias[t]       = b_ih[t]       + b_hh[t];
        g_bias[t + 256] = b_ih[t + 256] + b_hh[t + 256];
    }
}

// ---------------------------------------------------------------------------
// Main kernel: 2 batch elements per CTA, 1024 threads, 256 LSTM steps.
// LSTM gate GEMV on the TENSOR pipe: warp w owns gates 16w..16w+15; A-frags
// (weights) resident in 32 b32 regs; B = h in fp16 rebuilt per step from a
// 512 B smem array (2 LDS.32 per k-chunk). Attention collapsed to per-batch
// lerp tables (built once).
// ---------------------------------------------------------------------------
__global__ __launch_bounds__(1024, 1)
void decoder_kernel(const float* __restrict__ enc,   // [B,S,E]
                    const float* __restrict__ W1_b,  // [S]
                    const float* __restrict__ W2_w,  // [S,2S]
                    const float* __restrict__ W2_b,  // [S]
                    const float* __restrict__ W_ih,  // [4D,E]
                    float* __restrict__ out)         // [S,B,D]
{
    __shared__ __align__(16) float4 sAC[2][128];
    __shared__ __align__(16) float4 sE[2][128];
    __shared__ __align__(16) float  ebuf[1024];
    __shared__ float a_st[2][256];
    __shared__ __align__(16) float4 Ttab[2][TN];   // {g0x,g0y,dgx,dgy}
    __shared__ float2 tail2[2];
    __shared__ __align__(16) float2 gatesP[GG];    // {gate_m0, gate_m1}
    __shared__ __align__(16) float h_s[2][DD];     // f32 h (for lookup)
    __shared__ __align__(8)  __half hh[2][DD];     // fp16 h (mma B operand)
    __shared__ __align__(16) float2 wred[2][4];
    __shared__ __align__(16) float2 wihs[GG];
    __shared__ float sbias[GG];

    const int bid = blockIdx.x;
    const int t = threadIdx.x;        // 0..1023
    const int lane = t & 31;
    const int warp = t >> 5;

    // ---- init loads ----
    ebuf[t] = enc[bid * 1024 + t];
    if (t < GG) { wihs[t] = ((const float2*)W_ih)[t]; sbias[t] = g_bias[t]; }
    if (t < 256) {
        h_s[t >> 7][t & 127] = 0.f;
        hh[t >> 7][t & 127] = __float2half_rn(0.f);
    }
    __syncthreads();

    // a[m][s] = encflat[m] . W2_w[s,:] + W2_b[s] + W1_b[s]; 32 warps x 16 rows
    {
        const int m_w = warp >> 4;                  // warps 0-15: m=0, 16-31: m=1
        const float4* W2w4 = (const float4*)W2_w;
        const float4* e4   = (const float4*)(ebuf + m_w * 512);
        for (int r = 0; r < 16; r++) {
            int s = (warp & 15) * 16 + r;
            float acc = 0.f;
            #pragma unroll
            for (int i = 0; i < 4; i++) {
                float4 wv = W2w4[s * 128 + lane + 32 * i];
                float4 ev = e4[lane + 32 * i];
                acc += wv.x * ev.x + wv.y * ev.y + wv.z * ev.z + wv.w * ev.w;
            }
            #pragma unroll
            for (int off = 16; off; off >>= 1)
                acc += __shfl_xor_sync(0xffffffffu, acc, off);
            if (lane == 0) a_st[m_w][s] = acc + W2_b[s] + W1_b[s];
        }
    }
    __syncthreads();
    if (t < 256) {
        int m = t >> 7, p = t & 127;
        sAC[m][p] = make_float4(a_st[m][2 * p], a_st[m][2 * p + 1],
                                g_w1sum[2 * p], g_w1sum[2 * p + 1]);
        sE[m][p]  = make_float4(ebuf[m * 512 + 4 * p],     ebuf[m * 512 + 4 * p + 2],
                                ebuf[m * 512 + 4 * p + 1], ebuf[m * 512 + 4 * p + 3]);
    }
    __syncthreads();

    // Degree-5 Chebyshev-economized poly for exp(t), t in [-1,1], abs err <= 5e-5
    const unsigned long long P5 = pack2(0.00868688f, 0.00868688f);
    const unsigned long long P4 = pack2(0.04379392f, 0.04379392f);
    const unsigned long long P3 = pack2(0.16648880f, 0.16648880f);
    const unsigned long long P2 = pack2(0.49919676f, 0.49919676f);
    const unsigned long long P1 = pack2(1.00002231f, 1.00002231f);
    const unsigned long long P0 = pack2(1.00004478f, 1.00004478f);

    // ---- build lookup tables ----
    for (int idx = t; idx < 2 * (TN + 1); idx += 1024) {
        int m = (idx > TN) ? 1 : 0;
        int k = idx - m * (TN + 1);
        const double2* pAC = (const double2*)sAC[m];
        const double2* pE  = (const double2*)sE[m];
        float h = fmaf((float)k, 2.0f / TN, -1.0f);
        unsigned long long hd2;
        asm("mov.b64 %0, {%1,%1};" : "=l"(hd2) : "f"(h));
        unsigned long long Z2 = 0ull, n02 = 0ull, n12 = 0ull;
        #pragma unroll 4
        for (int i = 0; i < 128; i++) {
            double2 acd = pAC[i];
            double2 eed = pE[i];
            unsigned long long ap  = __double_as_longlong(acd.x);
            unsigned long long cp  = __double_as_longlong(acd.y);
            unsigned long long e0p = __double_as_longlong(eed.x);
            unsigned long long e1p = __double_as_longlong(eed.y);
            unsigned long long x2;
            asm("fma.rn.f32x2 %0, %1, %2, %3;" : "=l"(x2) : "l"(hd2), "l"(cp), "l"(ap));
            float x0, x1;
            asm("mov.b64 {%0,%1}, %2;" : "=f"(x0), "=f"(x1) : "l"(x2));
            float t0 = tanh_fast(x0);
            float t1 = tanh_fast(x1);
            unsigned long long t2;
            asm("mov.b64 %0, {%1,%2};" : "=l"(t2) : "f"(t0), "f"(t1));
            unsigned long long p;
            asm("fma.rn.f32x2 %0, %1, %2, %3;" : "=l"(p) : "l"(P5), "l"(t2), "l"(P4));
            asm("fma.rn.f32x2 %0, %0, %1, %2;" : "+l"(p) : "l"(t2), "l"(P3));
            asm("fma.rn.f32x2 %0, %0, %1, %2;" : "+l"(p) : "l"(t2), "l"(P2));
            asm("fma.rn.f32x2 %0, %0, %1, %2;" : "+l"(p) : "l"(t2), "l"(P1));
            asm("fma.rn.f32x2 %0, %0, %1, %2;" : "+l"(p) : "l"(t2), "l"(P0));
            asm("add.rn.f32x2 %0, %0, %1;"     : "+l"(Z2) : "l"(p));
            asm("fma.rn.f32x2 %0, %1, %2, %0;" : "+l"(n02) : "l"(p), "l"(e0p));
            asm("fma.rn.f32x2 %0, %1, %2, %0;" : "+l"(n12) : "l"(p), "l"(e1p));
        }
        float Zl, Zh, a0, a1, b0, b1;
        asm("mov.b64 {%0,%1}, %2;" : "=f"(Zl), "=f"(Zh) : "l"(Z2));
        asm("mov.b64 {%0,%1}, %2;" : "=f"(a0), "=f"(a1) : "l"(n02));
        asm("mov.b64 {%0,%1}, %2;" : "=f"(b0), "=f"(b1) : "l"(n12));
        float Z = Zl + Zh, n0 = a0 + a1, n1 = b0 + b1;
        float inv = __fdividef(1.f, Z);
        float gx = n0 * inv, gy = n1 * inv;
        if (k < TN) { Ttab[m][k].x = gx; Ttab[m][k].y = gy; }
        else        { tail2[m] = make_float2(gx, gy); }
    }
    __syncthreads();
    {   // slopes: exactly 1024 items = 1 per thread
        int m = t >> 9, k = t & (TN - 1);
        float2 cur = *(const float2*)&Ttab[m][k];
        float2 nxt = (k == TN - 1) ? tail2[m] : *(const float2*)&Ttab[m][k + 1];
        __syncthreads();
        Ttab[m][k].z = nxt.x - cur.x;
        Ttab[m][k].w = nxt.y - cur.y;
    }
    __syncthreads();

    // ---- mma roles + resident A-fragments (32 b32 regs) ----
    const int g = lane >> 2;          // group id 0..7
    const int q = lane & 3;           // thread-in-group
    unsigned int Af[32];
    {
        const uint4* wf = ((const uint4*)g_Wfrag) + t;
        #pragma unroll
        for (int c = 0; c < 8; c++) {
            uint4 v = wf[c * 1024];   // coalesced, one-time
            Af[4 * c + 0] = v.x;
            Af[4 * c + 1] = v.y;
            Af[4 * c + 2] = v.z;
            Af[4 * c + 3] = v.w;
        }
    }
    // B operand source: batch column n = g (cols >=2 duplicate batch g&1)
    const __half* hbase = hh[g & 1] + 2 * q;
    const int row0 = 16 * warp + g;   // gates this thread's C frag covers
    float c_reg = 0.f;                // cell state for epilogue threads (0..255)

    for (int step = 0; step < SS; step++) {
        // ---- Phase 1a: gate GEMV on tensor pipe ----
        float c0 = 0.f, c1 = 0.f, c2 = 0.f, c3 = 0.f;
        #pragma unroll
        for (int c = 0; c < 8; c++) {
            unsigned int b0 = *(const unsigned int*)(hbase + 16 * c);      // k {16c+2q,+1}
            unsigned int b1 = *(const unsigned int*)(hbase + 16 * c + 8);  // k {+8,+9}
            asm volatile(
                "mma.sync.aligned.m16n8k16.row.col.f32.f16.f16.f32 "
                "{%0,%1,%2,%3}, {%4,%5,%6,%7}, {%8,%9}, {%0,%1,%2,%3};"
                : "+f"(c0), "+f"(c1), "+f"(c2), "+f"(c3)
                : "r"(Af[4 * c]), "r"(Af[4 * c + 1]),
                  "r"(Af[4 * c + 2]), "r"(Af[4 * c + 3]),
                  "r"(b0), "r"(b1));
        }
        if (q == 0) {                 // cols 0,1 = batches 0,1
            gatesP[row0]     = make_float2(c0, c1);
            gatesP[row0 + 8] = make_float2(c2, c3);
        }

        // ---- Phase 1b: attention lookup (warps 8..15: one (m,d) each) ----
        if (t >= 256 && t < 512) {
            int tt = t - 256;
            int m = tt >> 7, d2 = tt & 127;
            float h = h_s[m][d2];
            float uu = fmaf(h, (float)(TN / 2), (float)(TN / 2));
            int i = (int)uu;
            i = max(0, min(i, TN - 1));
            float f = uu - (float)i;
            float4 tv = Ttab[m][i];
            float gx = fmaf(f, tv.z, tv.x);
            float gy = fmaf(f, tv.w, tv.y);
            #pragma unroll
            for (int off = 16; off; off >>= 1) {
                gx += __shfl_xor_sync(0xffffffffu, gx, off);
                gy += __shfl_xor_sync(0xffffffffu, gy, off);
            }
            if (lane == 0) wred[m][(warp - 8) & 3] = make_float2(gx, gy);
        }
        __syncthreads();                         // B1

        // ---- Phase 2: ctx-combine + LSTM update (threads 0..255) ----
        if (t < 256) {
            int m = t >> 7, d = t & 127;
            float2 r0 = wred[m][0], r1 = wred[m][1], r2 = wred[m][2], r3 = wred[m][3];
            float x0c = (r0.x + r1.x + r2.x + r3.x) * (1.f / 128.f);
            float x1c = (r0.y + r1.y + r2.y + r3.y) * (1.f / 128.f);
            float2 gp0 = gatesP[d];
            float2 gp1 = gatesP[d + 128];
            float2 gp2 = gatesP[d + 256];
            float2 gp3 = gatesP[d + 384];
            float2 wi0 = wihs[d];
            float2 wi1 = wihs[d + 128];
            float2 wi2 = wihs[d + 256];
            float2 wi3 = wihs[d + 384];
            float gi = (m ? gp0.y : gp0.x) + sbias[d]       + x0c * wi0.x + x1c * wi0.y;
            float gf = (m ? gp1.y : gp1.x) + sbias[d + 128] + x0c * wi1.x + x1c * wi1.y;
            float gg = (m ? gp2.y : gp2.x) + sbias[d + 256] + x0c * wi2.x + x1c * wi2.y;
            float go = (m ? gp3.y : gp3.x) + sbias[d + 384] + x0c * wi3.x + x1c * wi3.y;
            float si = sigmoid_fast(gi);
            float sf = sigmoid_fast(gf);
            float so = sigmoid_fast(go);
            c_reg = fmaf(sf, c_reg, si * tanh_fast(gg));
            float h = so * tanh_fast(c_reg);
            h_s[m][d] = h;
            hh[m][d] = __float2half_rn(h);
            out[(size_t)step * (BB * DD) + (2 * bid + m) * DD + d] = h;
        }
        __syncthreads();                         // B2
    }
}

// ---------------------------------------------------------------------------
extern "C" void kernel_launch(void* const* d_in, const int* in_sizes, int n_in,
                              void* d_out, int out_size) {
    const float* enc  = (const float*)d_in[0];
    const float* W1_w = (const float*)d_in[1];
    const float* W1_b = (const float*)d_in[2];
    const float* W2_w = (const float*)d_in[3];
    const float* W2_b = (const float*)d_in[4];
    const float* W_ih = (const float*)d_in[5];
    const float* W_hh = (const float*)d_in[6];
    const float* b_ih = (const float*)d_in[7];
    const float* b_hh = (const float*)d_in[8];
    float* out = (float*)d_out;

    prep_kernel<<<129, 256>>>(W1_w, W_hh, b_ih, b_hh);
    decoder_kernel<<<BB / 2, 1024>>>(enc, W1_b, W2_w, W2_b, W_ih, out);
}